// round 16
// baseline (speedup 1.0000x reference)
#include <cuda_runtime.h>
#include <cuda_bf16.h>
#include <cstdint>

// GRU_66314295050287 on GB300 (sm_103a) — R16: TMA bulk loads, no per-lane
// request stream. Diagnosis: every cp.async topology pinned at ~53% DRAM;
// the invariant mechanism is cross-CTA L1tex-queue contention from
// front-batched per-lane LDGSTS (spread ~1.2-1.3x per B300 model). Fix:
// cp.async.bulk (UBLKCP) — 32 copies of 1536B per block (one per seq) into
// a 1552B-strided smem slab, one mbarrier (expect_tx=48KB). TMA writes smem
// directly: zero L1tex wavefronts. No intra-block pipeline; overlap via 4
// co-resident blocks/SM (~192KB in flight/SM) across ~3.5 waves.

#define T_DIM        12
#define FE_DIM       32
#define SEQ_PER_BLK  32
#define NTHREADS     32
#define SEQ_FLOATS   384                         // 1536 B per sequence
#define SSTRIDE      388                         // 1552 B: 4l mod 32 -> conflict-free
#define DATA_OFF     160                         // floats; keeps data 16B-aligned
#define SMEM_FLOATS  (DATA_OFF + SEQ_PER_BLK * SSTRIDE)
#define TX_BYTES     (SEQ_PER_BLK * SEQ_FLOATS * 4)   // 49152

__device__ __forceinline__ float fast_sigmoid(float x) {
    return 1.0f / (1.0f + __expf(-x));
}
__device__ __forceinline__ float fast_tanh(float x) {
    float e = __expf(2.0f * x);
    return 1.0f - 2.0f / (1.0f + e);
}

__device__ __forceinline__ void mbar_init(unsigned int mbar, unsigned int count) {
    asm volatile("mbarrier.init.shared.b64 [%0], %1;" :: "r"(mbar), "r"(count) : "memory");
}
__device__ __forceinline__ void mbar_expect_tx(unsigned int mbar, unsigned int bytes) {
    asm volatile("mbarrier.arrive.expect_tx.shared.b64 _, [%0], %1;"
                 :: "r"(mbar), "r"(bytes) : "memory");
}
__device__ __forceinline__ void bulk_g2s(unsigned int dst, const void* src,
                                         unsigned int bytes, unsigned int mbar) {
    asm volatile("cp.async.bulk.shared::cta.global.mbarrier::complete_tx::bytes "
                 "[%0], [%1], %2, [%3];"
                 :: "r"(dst), "l"(src), "r"(bytes), "r"(mbar) : "memory");
}
__device__ __forceinline__ void mbar_wait_parity0(unsigned int mbar) {
    asm volatile(
        "{\n\t"
        ".reg .pred P1;\n\t"
        "WAIT_LOOP_%=:\n\t"
        "mbarrier.try_wait.parity.acquire.cta.shared::cta.b64 P1, [%0], 0, 0x989680;\n\t"
        "@P1 bra.uni WAIT_DONE_%=;\n\t"
        "bra.uni WAIT_LOOP_%=;\n\t"
        "WAIT_DONE_%=:\n\t"
        "}"
        :: "r"(mbar) : "memory");
}

extern __shared__ float smem[];

__global__ void __launch_bounds__(NTHREADS, 4)
gru_kernel(const float* __restrict__ x,
           const float* __restrict__ w_ih,   // [3][32]
           const float* __restrict__ w_hh,   // [3][1]
           const float* __restrict__ b_ih,   // [3]
           const float* __restrict__ b_hh,   // [3]
           const float* __restrict__ lin_w,  // [3][12]
           const float* __restrict__ lin_b,  // [3]
           float* __restrict__ out)          // [M][3]
{
    // Layout: [0:2) mbarrier (8B), [4:100) w_ih, [100:136) lin_w,
    //         [DATA_OFF:...) 32 seq x 388-float padded rows.
    float* s_wih  = smem + 4;
    float* s_lw   = smem + 100;
    float* sdata  = smem + DATA_OFF;

    const int tid = threadIdx.x;
    const unsigned int sbase = (unsigned int)__cvta_generic_to_shared(smem);
    const unsigned int mbar  = sbase;                       // smem[0..1]
    const unsigned int sdata_sa = sbase + DATA_OFF * 4;

    const int m0 = blockIdx.x * SEQ_PER_BLK;

    // Weights via regular loads (tiny, L2-hot after wave 1).
#pragma unroll
    for (int i = tid; i < 96; i += NTHREADS) s_wih[i] = w_ih[i];
#pragma unroll
    for (int i = tid; i < 36; i += NTHREADS) s_lw[i] = lin_w[i];

    if (tid == 0) mbar_init(mbar, 1);
    __syncthreads();                    // mbar visible before wait/copies

    if (tid == 0) {
        mbar_expect_tx(mbar, TX_BYTES);
        const char* gsrc = (const char*)(x) + (long)m0 * SEQ_FLOATS * 4;
#pragma unroll
        for (int m = 0; m < SEQ_PER_BLK; ++m) {
            bulk_g2s(sdata_sa + (unsigned int)(m * SSTRIDE * 4),
                     gsrc + (long)m * SEQ_FLOATS * 4,
                     SEQ_FLOATS * 4, mbar);
        }
    }

    mbar_wait_parity0(mbar);            // acquire: data visible to all lanes

    // Gate accumulation: thread tid owns seq tid (row tid*388 floats).
    const float bi0 = b_ih[0], bi1 = b_ih[1], bi2 = b_ih[2];
    float gx0[T_DIM], gx1[T_DIM], gx2[T_DIM];
#pragma unroll
    for (int t = 0; t < T_DIM; ++t) { gx0[t] = bi0; gx1[t] = bi1; gx2[t] = bi2; }

    const float* my = sdata + tid * SSTRIDE;
#pragma unroll 8
    for (int f = 0; f < FE_DIM; ++f) {
        float w0 = s_wih[f];
        float w1 = s_wih[32 + f];
        float w2 = s_wih[64 + f];
        // Lane l, vector v: addr mod 32 floats = 4l + 12f + 4v -> the 8 lanes
        // of each LDS.128 phase hit 8 distinct bank-quads (conflict-free).
#pragma unroll
        for (int v = 0; v < 3; ++v) {
            float4 a = reinterpret_cast<const float4*>(my + f * T_DIM)[v];
            int tb = v * 4;
            gx0[tb+0] = fmaf(a.x, w0, gx0[tb+0]);
            gx1[tb+0] = fmaf(a.x, w1, gx1[tb+0]);
            gx2[tb+0] = fmaf(a.x, w2, gx2[tb+0]);
            gx0[tb+1] = fmaf(a.y, w0, gx0[tb+1]);
            gx1[tb+1] = fmaf(a.y, w1, gx1[tb+1]);
            gx2[tb+1] = fmaf(a.y, w2, gx2[tb+1]);
            gx0[tb+2] = fmaf(a.z, w0, gx0[tb+2]);
            gx1[tb+2] = fmaf(a.z, w1, gx1[tb+2]);
            gx2[tb+2] = fmaf(a.z, w2, gx2[tb+2]);
            gx0[tb+3] = fmaf(a.w, w0, gx0[tb+3]);
            gx1[tb+3] = fmaf(a.w, w1, gx1[tb+3]);
            gx2[tb+3] = fmaf(a.w, w2, gx2[tb+3]);
        }
    }

    // Scalar-hidden GRU recurrence + relu + linear head.
    const float wh0 = w_hh[0], wh1 = w_hh[1], wh2 = w_hh[2];
    const float bh0 = b_hh[0], bh1 = b_hh[1], bh2 = b_hh[2];
    float o0 = lin_b[0], o1 = lin_b[1], o2 = lin_b[2];
    float h = 0.0f;
#pragma unroll
    for (int t = 0; t < T_DIM; ++t) {
        float r = fast_sigmoid(gx0[t] + wh0 * h + bh0);
        float z = fast_sigmoid(gx1[t] + wh1 * h + bh1);
        float n = fast_tanh(gx2[t] + r * (wh2 * h + bh2));
        h = (1.0f - z) * n + z * h;
        float hr = fmaxf(h, 0.0f);
        o0 = fmaf(hr, s_lw[t],       o0);
        o1 = fmaf(hr, s_lw[12 + t],  o1);
        o2 = fmaf(hr, s_lw[24 + t],  o2);
    }

    // Coalesced epilogue: stage [32][3] floats, write 24 float4.
    __syncthreads();                    // all lanes done reading sdata
    float* s_out = sdata;
    s_out[tid * 3 + 0] = o0;            // stride 3 coprime with 32 -> conflict-free
    s_out[tid * 3 + 1] = o1;
    s_out[tid * 3 + 2] = o2;
    __syncthreads();
    if (tid < (SEQ_PER_BLK * 3) / 4) {
        reinterpret_cast<float4*>(out + (long)m0 * 3)[tid] =
            reinterpret_cast<const float4*>(s_out)[tid];
    }
}

extern "C" void kernel_launch(void* const* d_in, const int* in_sizes, int n_in,
                              void* d_out, int out_size) {
    const float* x     = (const float*)d_in[0];
    const float* w_ih  = (const float*)d_in[1];
    const float* w_hh  = (const float*)d_in[2];
    const float* b_ih  = (const float*)d_in[3];
    const float* b_hh  = (const float*)d_in[4];
    const float* lin_w = (const float*)d_in[5];
    const float* lin_b = (const float*)d_in[6];
    float* out = (float*)d_out;

    const int M = in_sizes[0] / (FE_DIM * T_DIM);   // 65536
    const int grid = M / SEQ_PER_BLK;               // 2048

    const size_t smem_bytes = (size_t)SMEM_FLOATS * sizeof(float);
    cudaFuncSetAttribute(gru_kernel, cudaFuncAttributeMaxDynamicSharedMemorySize,
                         (int)smem_bytes);

    gru_kernel<<<grid, NTHREADS, smem_bytes>>>(x, w_ih, w_hh, b_ih, b_hh,
                                               lin_w, lin_b, out);
}